// round 14
// baseline (speedup 1.0000x reference)
#include <cuda_runtime.h>
#include <cuda_bf16.h>
#include <cstdint>

#define NN 768
#define PP (NN*NN)

__device__ __align__(256) __nv_bfloat16 g_left [(size_t)128 * PP]; // [h][i*N+k]
__device__ __align__(256) __nv_bfloat16 g_right[(size_t)128 * PP]; // [h][j*N+k]
__device__ __align__(256) __nv_bfloat16 g_pair [(size_t)128 * PP]; // [d][i*N+j]
__device__ __align__(256) float         g_ogate[(size_t)PP  * 128]; // [p][h]
__device__ __align__(256) __nv_bfloat16 g_wh[6][128*128];           // weight hi
__device__ __align__(256) __nv_bfloat16 g_wlo[6][128*128];          // weight lo

// ---------------- mma helpers ----------------
__device__ __forceinline__ void mma16816(float* c, const uint32_t* a, const uint32_t* b) {
    asm volatile("mma.sync.aligned.m16n8k16.row.col.f32.bf16.bf16.f32 "
                 "{%0,%1,%2,%3}, {%4,%5,%6,%7}, {%8,%9}, {%0,%1,%2,%3};\n"
                 : "+f"(c[0]), "+f"(c[1]), "+f"(c[2]), "+f"(c[3])
                 : "r"(a[0]), "r"(a[1]), "r"(a[2]), "r"(a[3]), "r"(b[0]), "r"(b[1]));
}
__device__ __forceinline__ void ldsm4(uint32_t* r, const void* p) {
    unsigned a = (unsigned)__cvta_generic_to_shared(p);
    asm volatile("ldmatrix.sync.aligned.m8n8.x4.shared.b16 {%0,%1,%2,%3}, [%4];\n"
                 : "=r"(r[0]), "=r"(r[1]), "=r"(r[2]), "=r"(r[3]) : "r"(a));
}

// M(2x16) x N(NF x 8) x K128 split-bf16 GEMM: acc += X*W^T.
// Fused 3 passes (hh, hl, lh) per k-step: fragments loaded once, 3 mma each.
template<int NF>
__device__ __forceinline__ void gemm_tile3(
    float (&acc)[2][NF][4],
    const __nv_bfloat16* sXh, const __nv_bfloat16* sXl,
    const __nv_bfloat16* sWh, const __nv_bfloat16* sWl,
    int lane, int mbase, int nbase)
{
    const int lr  = lane & 15, lkA = (lane >> 4) << 3;
    const int bn  = lane & 7, bks = ((lane >> 3) & 1) << 3;
    const int bnf = lane >> 4;
    #pragma unroll
    for (int ks = 0; ks < 8; ks++) {
        uint32_t ah[2][4], al[2][4], bh[NF][2], bl[NF][2];
        #pragma unroll
        for (int mf = 0; mf < 2; mf++) {
            ldsm4(ah[mf], sXh + (mbase + mf*16 + lr)*136 + ks*16 + lkA);
            ldsm4(al[mf], sXl + (mbase + mf*16 + lr)*136 + ks*16 + lkA);
        }
        #pragma unroll
        for (int nf = 0; nf < NF; nf += 2) {
            uint32_t t[4];
            ldsm4(t, sWh + (nbase + (nf + bnf)*8 + bn)*136 + ks*16 + bks);
            bh[nf][0]=t[0]; bh[nf][1]=t[1]; bh[nf+1][0]=t[2]; bh[nf+1][1]=t[3];
            ldsm4(t, sWl + (nbase + (nf + bnf)*8 + bn)*136 + ks*16 + bks);
            bl[nf][0]=t[0]; bl[nf][1]=t[1]; bl[nf+1][0]=t[2]; bl[nf+1][1]=t[3];
        }
        #pragma unroll
        for (int mf = 0; mf < 2; mf++)
            #pragma unroll
            for (int nf = 0; nf < NF; nf++) {
                mma16816(acc[mf][nf], ah[mf], bh[nf]);
                mma16816(acc[mf][nf], ah[mf], bl[nf]);
                mma16816(acc[mf][nf], al[mf], bh[nf]);
            }
    }
}

// ---------------- Stage Wsplit: split 6 weight mats to bf16 hi/lo ----------------
__global__ void stage_wsplit(
    const float* __restrict__ wl, const float* __restrict__ wr,
    const float* __restrict__ wlg, const float* __restrict__ wrg,
    const float* __restrict__ wog, const float* __restrict__ wout)
{
    const float* Ws[6] = {wl, wr, wlg, wrg, wog, wout};
    const float* W = Ws[blockIdx.x];
    __nv_bfloat16* gh = g_wh[blockIdx.x];
    __nv_bfloat16* gl = g_wlo[blockIdx.x];
    for (int i = threadIdx.x; i < 128*128/2; i += 256) {
        float2 w = ((const float2*)W)[i];
        __nv_bfloat16 hx = __float2bfloat16_rn(w.x), hy = __float2bfloat16_rn(w.y);
        __nv_bfloat162 hp; hp.x = hx; hp.y = hy;
        ((__nv_bfloat162*)gh)[i] = hp;
        ((__nv_bfloat162*)gl)[i] =
            __floats2bfloat162_rn(w.x - __bfloat162float(hx), w.y - __bfloat162float(hy));
    }
}

// copy pre-split [128][128] weight hi/lo into smem tiles, pitch 136 (512 thr)
__device__ __forceinline__ void copy_w128_512(const __nv_bfloat16* __restrict__ gh,
                                              const __nv_bfloat16* __restrict__ gl,
                                              __nv_bfloat16* sh, __nv_bfloat16* sl, int tid) {
    #pragma unroll
    for (int q = 0; q < 4; q++) {
        int idx = tid + 512*q, row = idx >> 4, seg = (idx & 15) << 3;
        *(uint4*)(sh + row*136 + seg) = *(const uint4*)(gh + row*128 + seg);
        *(uint4*)(sl + row*136 + seg) = *(const uint4*)(gl + row*128 + seg);
    }
}

// ---- Stage A fused: LN + 5 projections + gating, X resident, M=128, 512 thr ----
#define AM_SMEM (4*34816)   // X hi/lo + W hi/lo, each [128][136] bf16 = 136 KB

__global__ __launch_bounds__(512, 1) void stage_a_fused(
    const float* __restrict__ x,   const float* __restrict__ mask,
    const float* __restrict__ nw,  const float* __restrict__ nb)
{
    extern __shared__ __nv_bfloat16 smem[];
    __nv_bfloat16* sXh = smem;            // [128][136]  (live whole kernel)
    __nv_bfloat16* sXl = smem + 17408;
    __nv_bfloat16* sWh = smem + 34816;    // [128][136] (recycled per weight)
    __nv_bfloat16* sWl = smem + 52224;

    const int tid = threadIdx.x, lane = tid & 31, warp = tid >> 5;
    const int wm = warp & 3, wn = warp >> 2;
    const size_t pbase = (size_t)blockIdx.x * 128;

    { // LayerNorm straight from gmem into sXh/sXl, warp per position
        float4 w4 = ((const float4*)nw)[lane], b4 = ((const float4*)nb)[lane];
        #pragma unroll 1
        for (int pp = 0; pp < 8; pp++) {
            int pos = warp*8 + pp;
            float4 v = ((const float4*)(x + (pbase+pos)*128))[lane];
            float s  = v.x+v.y+v.z+v.w;
            float sq = v.x*v.x+v.y*v.y+v.z*v.z+v.w*v.w;
            #pragma unroll
            for (int o = 16; o; o >>= 1) {
                s  += __shfl_xor_sync(~0u, s,  o);
                sq += __shfl_xor_sync(~0u, sq, o);
            }
            float mu = s*(1.f/128.f), var = sq*(1.f/128.f) - mu*mu;
            float rstd = rsqrtf(var + 1e-5f);
            v.x=(v.x-mu)*rstd*w4.x+b4.x; v.y=(v.y-mu)*rstd*w4.y+b4.y;
            v.z=(v.z-mu)*rstd*w4.z+b4.z; v.w=(v.w-mu)*rstd*w4.w+b4.w;
            __nv_bfloat16 hx=__float2bfloat16_rn(v.x), hy=__float2bfloat16_rn(v.y);
            __nv_bfloat16 hz=__float2bfloat16_rn(v.z), hw=__float2bfloat16_rn(v.w);
            __nv_bfloat162 h01; h01.x=hx; h01.y=hy;
            __nv_bfloat162 h23; h23.x=hz; h23.y=hw;
            __nv_bfloat162 l01 = __floats2bfloat162_rn(v.x-__bfloat162float(hx), v.y-__bfloat162float(hy));
            __nv_bfloat162 l23 = __floats2bfloat162_rn(v.z-__bfloat162float(hz), v.w-__bfloat162float(hw));
            *(__nv_bfloat162*)(sXh + pos*136 + lane*4)     = h01;
            *(__nv_bfloat162*)(sXh + pos*136 + lane*4 + 2) = h23;
            *(__nv_bfloat162*)(sXl + pos*136 + lane*4)     = l01;
            *(__nv_bfloat162*)(sXl + pos*136 + lane*4 + 2) = l23;
        }
    }

    float mrow[2][2];
    #pragma unroll
    for (int mf = 0; mf < 2; mf++) {
        int r = wm*32 + mf*16 + (lane >> 2);
        mrow[mf][0] = mask[pbase + r];
        mrow[mf][1] = mask[pbase + r + 8];
    }

    #pragma unroll 1
    for (int mat = 0; mat < 3; mat++) {
        const bool dual = (mat < 2);
        const int ia = (mat==0) ? 0 : (mat==1) ? 1 : 4;   // wl, wr, wog
        const int ib = (mat==0) ? 2 : 3;                  // wlg, wrg

        __syncthreads();                 // X ready (mat 0) / prior epilogue reads done
        copy_w128_512(g_wh[ia], g_wlo[ia], sWh, sWl, tid);
        __syncthreads();
        float accA[2][4][4] = {};
        gemm_tile3<4>(accA, sXh, sXl, sWh, sWl, lane, wm*32, wn*32);

        if (dual) {
            __syncthreads();             // WA reads done
            copy_w128_512(g_wh[ib], g_wlo[ib], sWh, sWl, tid);
            __syncthreads();
            float accB[2][4][4] = {};
            gemm_tile3<4>(accB, sXh, sXl, sWh, sWl, lane, wm*32, wn*32);

            __nv_bfloat16* s_stage = sWh;  // [128 h][132 pos], W dead after gemms
            __syncthreads();
            #pragma unroll
            for (int mf = 0; mf < 2; mf++)
                #pragma unroll
                for (int nf = 0; nf < 4; nf++) {
                    int row = wm*32 + mf*16 + (lane >> 2);
                    int col = wn*32 + nf*8 + (lane & 3)*2;
                    float g0 = 1.f/(1.f+__expf(-accB[mf][nf][0]));
                    float g1 = 1.f/(1.f+__expf(-accB[mf][nf][1]));
                    float g2 = 1.f/(1.f+__expf(-accB[mf][nf][2]));
                    float g3 = 1.f/(1.f+__expf(-accB[mf][nf][3]));
                    s_stage[ col   *132 + row  ] = __float2bfloat16(accA[mf][nf][0]*mrow[mf][0]*g0);
                    s_stage[(col+1)*132 + row  ] = __float2bfloat16(accA[mf][nf][1]*mrow[mf][0]*g1);
                    s_stage[ col   *132 + row+8] = __float2bfloat16(accA[mf][nf][2]*mrow[mf][1]*g2);
                    s_stage[(col+1)*132 + row+8] = __float2bfloat16(accA[mf][nf][3]*mrow[mf][1]*g3);
                }
            __syncthreads();
            __nv_bfloat16* gdst = (mat == 0) ? g_left : g_right;
            #pragma unroll
            for (int q = 0; q < 8; q++) {   // 128 h x 32 uint2-segs = 4096 / 512 thr
                int idx = tid + 512*q, hh = idx >> 5, seg = (idx & 31) << 2;
                *(uint2*)(gdst + (size_t)hh*PP + pbase + seg) =
                    *(const uint2*)(s_stage + hh*132 + seg);
            }
        } else {
            #pragma unroll
            for (int mf = 0; mf < 2; mf++)
                #pragma unroll
                for (int nf = 0; nf < 4; nf++) {
                    int row = wm*32 + mf*16 + (lane >> 2);
                    int col = wn*32 + nf*8 + (lane & 3)*2;
                    float2 p0 = make_float2(1.f/(1.f+__expf(-accA[mf][nf][0])),
                                            1.f/(1.f+__expf(-accA[mf][nf][1])));
                    float2 p1 = make_float2(1.f/(1.f+__expf(-accA[mf][nf][2])),
                                            1.f/(1.f+__expf(-accA[mf][nf][3])));
                    *(float2*)(g_ogate + (pbase+row)*128 + col)   = p0;
                    *(float2*)(g_ogate + (pbase+row+8)*128 + col) = p1;
                }
        }
    }
}

// -------- Stage B: per-channel bf16 einsum, k-chunk 64, one sync/iter --------
#define SB_SMEM (4*128*72*2)   // 73728 B -> 2 CTAs/SM

__device__ __forceinline__ void cpa16(void* dst, const void* src) {
    unsigned u = (unsigned)__cvta_generic_to_shared(dst);
    asm volatile("cp.async.cg.shared.global [%0], [%1], 16;\n" :: "r"(u), "l"(src) : "memory");
}
__device__ __forceinline__ void sb_issue(const __nv_bfloat16* gA, const __nv_bfloat16* gB,
                                         __nv_bfloat16* sA, __nv_bfloat16* sB, int tid, int k0) {
    #pragma unroll
    for (int q = 0; q < 4; q++) {
        int idx = tid + 256*q, row = idx >> 3, seg = (idx & 7) << 3;
        cpa16(sA + row*72 + seg, gA + (size_t)row*NN + k0 + seg);
        cpa16(sB + row*72 + seg, gB + (size_t)row*NN + k0 + seg);
    }
    asm volatile("cp.async.commit_group;\n" ::: "memory");
}

__global__ __launch_bounds__(256, 2) void stage_b() {
    extern __shared__ __nv_bfloat16 smb[];
    __nv_bfloat16* sA = smb;              // [2 buf][128][72]
    __nv_bfloat16* sB = smb + 2*128*72;

    const int tid = threadIdx.x, lane = tid & 31, warp = tid >> 5;
    const int wm = warp & 1, wn = warp >> 1;
    const int d = blockIdx.y, ti = blockIdx.x / 6, tj = blockIdx.x % 6;
    const __nv_bfloat16* gA = g_left  + (size_t)d*PP + (size_t)(ti*128)*NN;
    const __nv_bfloat16* gB = g_right + (size_t)d*PP + (size_t)(tj*128)*NN;

    const int lr  = lane & 15, lkA = (lane >> 4) << 3;
    const int bn  = lane & 7, bks = ((lane >> 3) & 1) << 3;
    const int bnf = lane >> 4;

    float c[4][4][4] = {};
    sb_issue(gA, gB, sA, sB, tid, 0);

    #pragma unroll 1
    for (int kt = 0; kt < 12; kt++) {
        int buf = kt & 1;
        asm volatile("cp.async.wait_group 0;\n" ::: "memory");
        __syncthreads();   // chunk kt visible; all warps done reading buf^1
        if (kt < 11)
            sb_issue(gA, gB, sA + (buf^1)*9216, sB + (buf^1)*9216, tid, (kt+1)*64);
        const __nv_bfloat16* Ab = sA + buf*9216;
        const __nv_bfloat16* Bb = sB + buf*9216;
        #pragma unroll
        for (int kk = 0; kk < 4; kk++) {
            uint32_t a[4][4], b[4][2];
            #pragma unroll
            for (int fm = 0; fm < 4; fm++)
                ldsm4(a[fm], Ab + (wm*64 + fm*16 + lr)*72 + kk*16 + lkA);
            #pragma unroll
            for (int nf = 0; nf < 4; nf += 2) {
                uint32_t t[4];
                ldsm4(t, Bb + (wn*32 + (nf + bnf)*8 + bn)*72 + kk*16 + bks);
                b[nf][0]=t[0]; b[nf][1]=t[1]; b[nf+1][0]=t[2]; b[nf+1][1]=t[3];
            }
            #pragma unroll
            for (int fm = 0; fm < 4; fm++)
                #pragma unroll
                for (int fn = 0; fn < 4; fn++) mma16816(c[fm][fn], a[fm], b[fn]);
        }
    }

    __nv_bfloat16* gO = g_pair + (size_t)d*PP;
    #pragma unroll
    for (int fm = 0; fm < 4; fm++)
        #pragma unroll
        for (int fn = 0; fn < 4; fn++) {
            int r0 = ti*128 + wm*64 + fm*16 + (lane >> 2);
            int cc = tj*128 + wn*32 + fn*8 + (lane & 3)*2;
            *(__nv_bfloat162*)(gO + (size_t)r0*NN + cc) =
                __float22bfloat162_rn(make_float2(c[fm][fn][0], c[fm][fn][1]));
            *(__nv_bfloat162*)(gO + (size_t)(r0+8)*NN + cc) =
                __float22bfloat162_rn(make_float2(c[fm][fn][2], c[fm][fn][3]));
        }
}

// ------ Stage C (mma): LN over H + out_gate + final projection, M=64 ------
#define SC_SMEM (2*17408 + 2*34816)   // 102 KB -> 2 CTAs/SM

// copy pre-split weights, 256-thread variant
__device__ __forceinline__ void copy_w128(const __nv_bfloat16* __restrict__ gh,
                                          const __nv_bfloat16* __restrict__ gl,
                                          __nv_bfloat16* sh, __nv_bfloat16* sl, int tid) {
    #pragma unroll
    for (int q = 0; q < 8; q++) {
        int idx = tid + 256*q, row = idx >> 4, seg = (idx & 15) << 3;
        *(uint4*)(sh + row*136 + seg) = *(const uint4*)(gh + row*128 + seg);
        *(uint4*)(sl + row*136 + seg) = *(const uint4*)(gl + row*128 + seg);
    }
}

__global__ __launch_bounds__(256, 2) void stage_cmm(
    const float* __restrict__ onw, const float* __restrict__ onb,
    float* __restrict__ out)
{
    extern __shared__ __nv_bfloat16 smc[];
    __nv_bfloat16* s_vh = smc;            // [64 pos][136]
    __nv_bfloat16* s_vl = smc + 8704;
    __nv_bfloat16* s_wh = smc + 17408;    // [128 dout][136]
    __nv_bfloat16* s_wl = smc + 34816;
    __nv_bfloat16* s_t  = s_wh;           // [128 d][68] overlay, dead before w fill

    const int tid = threadIdx.x, lane = tid & 31, warp = tid >> 5;
    const int wm = warp & 1, wn = warp >> 1;
    const size_t p0 = (size_t)blockIdx.x * 64;

    #pragma unroll
    for (int q = 0; q < 8; q++) { // pair tile [128 d][64 pos]
        int idx = tid + 256*q, dd = idx >> 4, seg = (idx & 15) << 2;
        *(uint2*)(s_t + dd*68 + seg) = *(const uint2*)(g_pair + (size_t)dd*PP + p0 + seg);
    }
    __syncthreads();

    float lw[4], lb[4];
    #pragma unroll
    for (int q = 0; q < 4; q++) { lw[q] = onw[lane+32*q]; lb[q] = onb[lane+32*q]; }

    #pragma unroll 1
    for (int pp = 0; pp < 8; pp++) { // LN over d + gate, warp per position
        int pos = warp*8 + pp;
        float t[4];
        #pragma unroll
        for (int q = 0; q < 4; q++) t[q] = __bfloat162float(s_t[(lane+32*q)*68 + pos]);
        float s = t[0]+t[1]+t[2]+t[3];
        float sq = t[0]*t[0]+t[1]*t[1]+t[2]*t[2]+t[3]*t[3];
        #pragma unroll
        for (int o = 16; o; o >>= 1) {
            s  += __shfl_xor_sync(~0u, s,  o);
            sq += __shfl_xor_sync(~0u, sq, o);
        }
        float mu = s*(1.f/128.f), var = sq*(1.f/128.f) - mu*mu;
        float rstd = rsqrtf(var + 1e-5f);
        #pragma unroll
        for (int q = 0; q < 4; q++) {
            float v = (t[q]-mu)*rstd*lw[q] + lb[q];
            v *= g_ogate[(p0+pos)*128 + lane + 32*q];
            __nv_bfloat16 h = __float2bfloat16_rn(v);
            s_vh[pos*136 + lane + 32*q] = h;
            s_vl[pos*136 + lane + 32*q] = __float2bfloat16_rn(v - __bfloat162float(h));
        }
    }
    __syncthreads();  // LN reads of s_t done; safe to overwrite with w_out

    copy_w128(g_wh[5], g_wlo[5], s_wh, s_wl, tid);
    __syncthreads();

    float acc[2][4][4] = {};
    gemm_tile3<4>(acc, s_vh, s_vl, s_wh, s_wl, lane, wm*32, wn*32);

    #pragma unroll
    for (int mf = 0; mf < 2; mf++)
        #pragma unroll
        for (int nf = 0; nf < 4; nf++) {
            int row = wm*32 + mf*16 + (lane >> 2);
            int col = wn*32 + nf*8 + (lane & 3)*2;
            *(float2*)(out + (p0+row)*128 + col)   = make_float2(acc[mf][nf][0], acc[mf][nf][1]);
            *(float2*)(out + (p0+row+8)*128 + col) = make_float2(acc[mf][nf][2], acc[mf][nf][3]);
        }
}

// -----------------------------------------------------------------------------
extern "C" void kernel_launch(void* const* d_in, const int* in_sizes, int n_in,
                              void* d_out, int out_size) {
    (void)in_sizes; (void)n_in; (void)out_size;
    const float* x    = (const float*)d_in[0];
    const float* mask = (const float*)d_in[1];
    const float* nw   = (const float*)d_in[2];
    const float* nb   = (const float*)d_in[3];
    const float* wl   = (const float*)d_in[4];
    const float* wr   = (const float*)d_in[5];
    const float* wlg  = (const float*)d_in[6];
    const float* wrg  = (const float*)d_in[7];
    const float* wog  = (const float*)d_in[8];
    const float* onw  = (const float*)d_in[9];
    const float* onb  = (const float*)d_in[10];
    const float* wout = (const float*)d_in[11];
    float* out = (float*)d_out;

    cudaFuncSetAttribute(stage_a_fused, cudaFuncAttributeMaxDynamicSharedMemorySize, AM_SMEM);
    cudaFuncSetAttribute(stage_b,       cudaFuncAttributeMaxDynamicSharedMemorySize, SB_SMEM);
    cudaFuncSetAttribute(stage_cmm,     cudaFuncAttributeMaxDynamicSharedMemorySize, SC_SMEM);

    stage_wsplit<<<6, 256>>>(wl, wr, wlg, wrg, wog, wout);
    stage_a_fused<<<PP/128, 512, AM_SMEM>>>(x, mask, nw, nb);
    stage_b<<<dim3(36, 128), 256, SB_SMEM>>>();
    stage_cmm<<<PP/64, 256, SC_SMEM>>>(onw, onb, out);
}

// round 15
// speedup vs baseline: 1.0591x; 1.0591x over previous
#include <cuda_runtime.h>
#include <cuda_bf16.h>
#include <cstdint>

#define NN 768
#define PP (NN*NN)

__device__ __align__(256) __nv_bfloat16 g_left [(size_t)128 * PP]; // [h][i*N+k]
__device__ __align__(256) __nv_bfloat16 g_right[(size_t)128 * PP]; // [h][j*N+k]
__device__ __align__(256) __nv_bfloat16 g_pair [(size_t)128 * PP]; // [d][i*N+j]
__device__ __align__(256) float         g_ogate[(size_t)PP  * 128]; // [p][h]
__device__ __align__(256) __nv_bfloat16 g_wh[6][128*128];           // weight hi
__device__ __align__(256) __nv_bfloat16 g_wlo[6][128*128];          // weight lo

// ---------------- mma helpers ----------------
__device__ __forceinline__ void mma16816(float* c, const uint32_t* a, const uint32_t* b) {
    asm volatile("mma.sync.aligned.m16n8k16.row.col.f32.bf16.bf16.f32 "
                 "{%0,%1,%2,%3}, {%4,%5,%6,%7}, {%8,%9}, {%0,%1,%2,%3};\n"
                 : "+f"(c[0]), "+f"(c[1]), "+f"(c[2]), "+f"(c[3])
                 : "r"(a[0]), "r"(a[1]), "r"(a[2]), "r"(a[3]), "r"(b[0]), "r"(b[1]));
}
__device__ __forceinline__ void ldsm4(uint32_t* r, const void* p) {
    unsigned a = (unsigned)__cvta_generic_to_shared(p);
    asm volatile("ldmatrix.sync.aligned.m8n8.x4.shared.b16 {%0,%1,%2,%3}, [%4];\n"
                 : "=r"(r[0]), "=r"(r[1]), "=r"(r[2]), "=r"(r[3]) : "r"(a));
}
__device__ __forceinline__ void cpa16(void* dst, const void* src) {
    unsigned u = (unsigned)__cvta_generic_to_shared(dst);
    asm volatile("cp.async.cg.shared.global [%0], [%1], 16;\n" :: "r"(u), "l"(src) : "memory");
}
__device__ __forceinline__ void cp_commit() {
    asm volatile("cp.async.commit_group;\n" ::: "memory");
}
__device__ __forceinline__ void cp_wait0() {
    asm volatile("cp.async.wait_group 0;\n" ::: "memory");
}

// M(2x16) x N(NF x 8) x K128 split-bf16 GEMM: acc += X*W^T.
// Fused 3 passes (hh, hl, lh) per k-step: fragments loaded once, 3 mma each.
template<int NF>
__device__ __forceinline__ void gemm_tile3(
    float (&acc)[2][NF][4],
    const __nv_bfloat16* sXh, const __nv_bfloat16* sXl,
    const __nv_bfloat16* sWh, const __nv_bfloat16* sWl,
    int lane, int mbase, int nbase)
{
    const int lr  = lane & 15, lkA = (lane >> 4) << 3;
    const int bn  = lane & 7, bks = ((lane >> 3) & 1) << 3;
    const int bnf = lane >> 4;
    #pragma unroll
    for (int ks = 0; ks < 8; ks++) {
        uint32_t ah[2][4], al[2][4], bh[NF][2], bl[NF][2];
        #pragma unroll
        for (int mf = 0; mf < 2; mf++) {
            ldsm4(ah[mf], sXh + (mbase + mf*16 + lr)*136 + ks*16 + lkA);
            ldsm4(al[mf], sXl + (mbase + mf*16 + lr)*136 + ks*16 + lkA);
        }
        #pragma unroll
        for (int nf = 0; nf < NF; nf += 2) {
            uint32_t t[4];
            ldsm4(t, sWh + (nbase + (nf + bnf)*8 + bn)*136 + ks*16 + bks);
            bh[nf][0]=t[0]; bh[nf][1]=t[1]; bh[nf+1][0]=t[2]; bh[nf+1][1]=t[3];
            ldsm4(t, sWl + (nbase + (nf + bnf)*8 + bn)*136 + ks*16 + bks);
            bl[nf][0]=t[0]; bl[nf][1]=t[1]; bl[nf+1][0]=t[2]; bl[nf+1][1]=t[3];
        }
        #pragma unroll
        for (int mf = 0; mf < 2; mf++)
            #pragma unroll
            for (int nf = 0; nf < NF; nf++) {
                mma16816(acc[mf][nf], ah[mf], bh[nf]);
                mma16816(acc[mf][nf], ah[mf], bl[nf]);
                mma16816(acc[mf][nf], al[mf], bh[nf]);
            }
    }
}

// ---------------- Stage Wsplit: split 6 weight mats to bf16 hi/lo ----------------
__global__ void stage_wsplit(
    const float* __restrict__ wl, const float* __restrict__ wr,
    const float* __restrict__ wlg, const float* __restrict__ wrg,
    const float* __restrict__ wog, const float* __restrict__ wout)
{
    const float* Ws[6] = {wl, wr, wlg, wrg, wog, wout};
    const float* W = Ws[blockIdx.x];
    __nv_bfloat16* gh = g_wh[blockIdx.x];
    __nv_bfloat16* gl = g_wlo[blockIdx.x];
    for (int i = threadIdx.x; i < 128*128/2; i += 256) {
        float2 w = ((const float2*)W)[i];
        __nv_bfloat16 hx = __float2bfloat16_rn(w.x), hy = __float2bfloat16_rn(w.y);
        __nv_bfloat162 hp; hp.x = hx; hp.y = hy;
        ((__nv_bfloat162*)gh)[i] = hp;
        ((__nv_bfloat162*)gl)[i] =
            __floats2bfloat162_rn(w.x - __bfloat162float(hx), w.y - __bfloat162float(hy));
    }
}

// async copy of pre-split [128][128] weight hi/lo into smem (pitch 136), 256 thr
__device__ __forceinline__ void copy_w128_async(const __nv_bfloat16* __restrict__ gh,
                                                const __nv_bfloat16* __restrict__ gl,
                                                __nv_bfloat16* sh, __nv_bfloat16* sl, int tid) {
    #pragma unroll
    for (int q = 0; q < 8; q++) {
        int idx = tid + 256*q, row = idx >> 4, seg = (idx & 15) << 3;
        cpa16(sh + row*136 + seg, gh + row*128 + seg);
        cpa16(sl + row*136 + seg, gl + row*128 + seg);
    }
    cp_commit();
}
// sync copy (stage_cmm, unchanged from R12)
__device__ __forceinline__ void copy_w128(const __nv_bfloat16* __restrict__ gh,
                                          const __nv_bfloat16* __restrict__ gl,
                                          __nv_bfloat16* sh, __nv_bfloat16* sl, int tid) {
    #pragma unroll
    for (int q = 0; q < 8; q++) {
        int idx = tid + 256*q, row = idx >> 4, seg = (idx & 15) << 3;
        *(uint4*)(sh + row*136 + seg) = *(const uint4*)(gh + row*128 + seg);
        *(uint4*)(sl + row*136 + seg) = *(const uint4*)(gl + row*128 + seg);
    }
}

// ---- Stage A fused: LN + 5 projections + gating, X resident, M=64, 2 CTAs/SM ----
#define AM_SMEM (2*17408 + 2*34816)   // 102 KB

__global__ __launch_bounds__(256, 2) void stage_a_fused(
    const float* __restrict__ x,   const float* __restrict__ mask,
    const float* __restrict__ nw,  const float* __restrict__ nb)
{
    extern __shared__ __nv_bfloat16 smem[];
    __nv_bfloat16* sXh = smem;            // [64][136]  (live whole kernel)
    __nv_bfloat16* sXl = smem + 8704;
    __nv_bfloat16* sWh = smem + 17408;    // [128][136] (recycled per weight)
    __nv_bfloat16* sWl = smem + 34816;

    const int tid = threadIdx.x, lane = tid & 31, warp = tid >> 5;
    const int wm = warp & 1, wn = warp >> 1;
    const size_t pbase = (size_t)blockIdx.x * 64;

    // Prefetch mat0 weights (wl) — overlaps the whole LN phase
    copy_w128_async(g_wh[0], g_wlo[0], sWh, sWl, tid);

    { // LayerNorm straight from gmem into sXh/sXl, warp per position
        float4 w4 = ((const float4*)nw)[lane], b4 = ((const float4*)nb)[lane];
        #pragma unroll 1
        for (int pp = 0; pp < 8; pp++) {
            int pos = warp*8 + pp;
            float4 v = ((const float4*)(x + (pbase+pos)*128))[lane];
            float s  = v.x+v.y+v.z+v.w;
            float sq = v.x*v.x+v.y*v.y+v.z*v.z+v.w*v.w;
            #pragma unroll
            for (int o = 16; o; o >>= 1) {
                s  += __shfl_xor_sync(~0u, s,  o);
                sq += __shfl_xor_sync(~0u, sq, o);
            }
            float mu = s*(1.f/128.f), var = sq*(1.f/128.f) - mu*mu;
            float rstd = rsqrtf(var + 1e-5f);
            v.x=(v.x-mu)*rstd*w4.x+b4.x; v.y=(v.y-mu)*rstd*w4.y+b4.y;
            v.z=(v.z-mu)*rstd*w4.z+b4.z; v.w=(v.w-mu)*rstd*w4.w+b4.w;
            __nv_bfloat16 hx=__float2bfloat16_rn(v.x), hy=__float2bfloat16_rn(v.y);
            __nv_bfloat16 hz=__float2bfloat16_rn(v.z), hw=__float2bfloat16_rn(v.w);
            __nv_bfloat162 h01; h01.x=hx; h01.y=hy;
            __nv_bfloat162 h23; h23.x=hz; h23.y=hw;
            __nv_bfloat162 l01 = __floats2bfloat162_rn(v.x-__bfloat162float(hx), v.y-__bfloat162float(hy));
            __nv_bfloat162 l23 = __floats2bfloat162_rn(v.z-__bfloat162float(hz), v.w-__bfloat162float(hw));
            *(__nv_bfloat162*)(sXh + pos*136 + lane*4)     = h01;
            *(__nv_bfloat162*)(sXh + pos*136 + lane*4 + 2) = h23;
            *(__nv_bfloat162*)(sXl + pos*136 + lane*4)     = l01;
            *(__nv_bfloat162*)(sXl + pos*136 + lane*4 + 2) = l23;
        }
    }

    float mrow[2][2];
    #pragma unroll
    for (int mf = 0; mf < 2; mf++) {
        int r = wm*32 + mf*16 + (lane >> 2);
        mrow[mf][0] = mask[pbase + r];
        mrow[mf][1] = mask[pbase + r + 8];
    }

    #pragma unroll 1
    for (int mat = 0; mat < 3; mat++) {
        const bool dual = (mat < 2);
        const int ib = (mat==0) ? 2 : 3;                  // wlg, wrg

        // mats 1,2: WA copy was issued at end of previous iteration
        cp_wait0();
        __syncthreads();                 // X + WA ready; prior epilogue done
        float accA[2][4][4] = {};
        gemm_tile3<4>(accA, sXh, sXl, sWh, sWl, lane, wm*32, wn*32);

        if (dual) {
            __syncthreads();             // all WA reads done
            copy_w128_async(g_wh[ib], g_wlo[ib], sWh, sWl, tid);
            cp_wait0();
            __syncthreads();
            float accB[2][4][4] = {};
            gemm_tile3<4>(accB, sXh, sXl, sWh, sWl, lane, wm*32, wn*32);

            __nv_bfloat16* s_stage = sWh;  // [128 h][68 pos], W dead after gemms
            __syncthreads();
            #pragma unroll
            for (int mf = 0; mf < 2; mf++)
                #pragma unroll
                for (int nf = 0; nf < 4; nf++) {
                    int row = wm*32 + mf*16 + (lane >> 2);
                    int col = wn*32 + nf*8 + (lane & 3)*2;
                    float g0 = 1.f/(1.f+__expf(-accB[mf][nf][0]));
                    float g1 = 1.f/(1.f+__expf(-accB[mf][nf][1]));
                    float g2 = 1.f/(1.f+__expf(-accB[mf][nf][2]));
                    float g3 = 1.f/(1.f+__expf(-accB[mf][nf][3]));
                    s_stage[ col   *68 + row  ] = __float2bfloat16(accA[mf][nf][0]*mrow[mf][0]*g0);
                    s_stage[(col+1)*68 + row  ] = __float2bfloat16(accA[mf][nf][1]*mrow[mf][0]*g1);
                    s_stage[ col   *68 + row+8] = __float2bfloat16(accA[mf][nf][2]*mrow[mf][1]*g2);
                    s_stage[(col+1)*68 + row+8] = __float2bfloat16(accA[mf][nf][3]*mrow[mf][1]*g3);
                }
            __syncthreads();
            __nv_bfloat16* gdst = (mat == 0) ? g_left : g_right;
            #pragma unroll
            for (int q = 0; q < 8; q++) {
                int idx = tid + 256*q, hh = idx >> 4, seg = (idx & 15) << 2;
                *(uint2*)(gdst + (size_t)hh*PP + pbase + seg) =
                    *(const uint2*)(s_stage + hh*68 + seg);
            }
            __syncthreads();             // s_stage reads done before next W copy
            const int nxt = (mat==0) ? 1 : 4;   // wr, wog
            copy_w128_async(g_wh[nxt], g_wlo[nxt], sWh, sWl, tid);
        } else {
            #pragma unroll
            for (int mf = 0; mf < 2; mf++)
                #pragma unroll
                for (int nf = 0; nf < 4; nf++) {
                    int row = wm*32 + mf*16 + (lane >> 2);
                    int col = wn*32 + nf*8 + (lane & 3)*2;
                    float2 p0 = make_float2(1.f/(1.f+__expf(-accA[mf][nf][0])),
                                            1.f/(1.f+__expf(-accA[mf][nf][1])));
                    float2 p1 = make_float2(1.f/(1.f+__expf(-accA[mf][nf][2])),
                                            1.f/(1.f+__expf(-accA[mf][nf][3])));
                    *(float2*)(g_ogate + (pbase+row)*128 + col)   = p0;
                    *(float2*)(g_ogate + (pbase+row+8)*128 + col) = p1;
                }
        }
    }
}

// -------- Stage B: per-channel bf16 einsum, k-chunk 64, one sync/iter --------
#define SB_SMEM (4*128*72*2)   // 73728 B -> 2 CTAs/SM

__device__ __forceinline__ void sb_issue(const __nv_bfloat16* gA, const __nv_bfloat16* gB,
                                         __nv_bfloat16* sA, __nv_bfloat16* sB, int tid, int k0) {
    #pragma unroll
    for (int q = 0; q < 4; q++) {
        int idx = tid + 256*q, row = idx >> 3, seg = (idx & 7) << 3;
        cpa16(sA + row*72 + seg, gA + (size_t)row*NN + k0 + seg);
        cpa16(sB + row*72 + seg, gB + (size_t)row*NN + k0 + seg);
    }
    cp_commit();
}

__global__ __launch_bounds__(256, 2) void stage_b() {
    extern __shared__ __nv_bfloat16 smb[];
    __nv_bfloat16* sA = smb;              // [2 buf][128][72]
    __nv_bfloat16* sB = smb + 2*128*72;

    const int tid = threadIdx.x, lane = tid & 31, warp = tid >> 5;
    const int wm = warp & 1, wn = warp >> 1;
    const int d = blockIdx.y, ti = blockIdx.x / 6, tj = blockIdx.x % 6;
    const __nv_bfloat16* gA = g_left  + (size_t)d*PP + (size_t)(ti*128)*NN;
    const __nv_bfloat16* gB = g_right + (size_t)d*PP + (size_t)(tj*128)*NN;

    const int lr  = lane & 15, lkA = (lane >> 4) << 3;
    const int bn  = lane & 7, bks = ((lane >> 3) & 1) << 3;
    const int bnf = lane >> 4;

    float c[4][4][4] = {};
    sb_issue(gA, gB, sA, sB, tid, 0);

    #pragma unroll 1
    for (int kt = 0; kt < 12; kt++) {
        int buf = kt & 1;
        cp_wait0();
        __syncthreads();   // chunk kt visible; all warps done reading buf^1
        if (kt < 11)
            sb_issue(gA, gB, sA + (buf^1)*9216, sB + (buf^1)*9216, tid, (kt+1)*64);
        const __nv_bfloat16* Ab = sA + buf*9216;
        const __nv_bfloat16* Bb = sB + buf*9216;
        #pragma unroll
        for (int kk = 0; kk < 4; kk++) {
            uint32_t a[4][4], b[4][2];
            #pragma unroll
            for (int fm = 0; fm < 4; fm++)
                ldsm4(a[fm], Ab + (wm*64 + fm*16 + lr)*72 + kk*16 + lkA);
            #pragma unroll
            for (int nf = 0; nf < 4; nf += 2) {
                uint32_t t[4];
                ldsm4(t, Bb + (wn*32 + (nf + bnf)*8 + bn)*72 + kk*16 + bks);
                b[nf][0]=t[0]; b[nf][1]=t[1]; b[nf+1][0]=t[2]; b[nf+1][1]=t[3];
            }
            #pragma unroll
            for (int fm = 0; fm < 4; fm++)
                #pragma unroll
                for (int fn = 0; fn < 4; fn++) mma16816(c[fm][fn], a[fm], b[fn]);
        }
    }

    __nv_bfloat16* gO = g_pair + (size_t)d*PP;
    #pragma unroll
    for (int fm = 0; fm < 4; fm++)
        #pragma unroll
        for (int fn = 0; fn < 4; fn++) {
            int r0 = ti*128 + wm*64 + fm*16 + (lane >> 2);
            int cc = tj*128 + wn*32 + fn*8 + (lane & 3)*2;
            *(__nv_bfloat162*)(gO + (size_t)r0*NN + cc) =
                __float22bfloat162_rn(make_float2(c[fm][fn][0], c[fm][fn][1]));
            *(__nv_bfloat162*)(gO + (size_t)(r0+8)*NN + cc) =
                __float22bfloat162_rn(make_float2(c[fm][fn][2], c[fm][fn][3]));
        }
}

// ------ Stage C (mma): LN over H + out_gate + final projection, M=64 ------
#define SC_SMEM (2*17408 + 2*34816)   // 102 KB -> 2 CTAs/SM

__global__ __launch_bounds__(256, 2) void stage_cmm(
    const float* __restrict__ onw, const float* __restrict__ onb,
    float* __restrict__ out)
{
    extern __shared__ __nv_bfloat16 smc[];
    __nv_bfloat16* s_vh = smc;            // [64 pos][136]
    __nv_bfloat16* s_vl = smc + 8704;
    __nv_bfloat16* s_wh = smc + 17408;    // [128 dout][136]
    __nv_bfloat16* s_wl = smc + 34816;
    __nv_bfloat16* s_t  = s_wh;           // [128 d][68] overlay, dead before w fill

    const int tid = threadIdx.x, lane = tid & 31, warp = tid >> 5;
    const int wm = warp & 1, wn = warp >> 1;
    const size_t p0 = (size_t)blockIdx.x * 64;

    #pragma unroll
    for (int q = 0; q < 8; q++) { // pair tile [128 d][64 pos]
        int idx = tid + 256*q, dd = idx >> 4, seg = (idx & 15) << 2;
        *(uint2*)(s_t + dd*68 + seg) = *(const uint2*)(g_pair + (size_t)dd*PP + p0 + seg);
    }
    __syncthreads();

    float lw[4], lb[4];
    #pragma unroll
    for (int q = 0; q < 4; q++) { lw[q] = onw[lane+32*q]; lb[q] = onb[lane+32*q]; }

    #pragma unroll 1
    for (int pp = 0; pp < 8; pp++) { // LN over d + gate, warp per position
        int pos = warp*8 + pp;
        float t[4];
        #pragma unroll
        for (int q = 0; q < 4; q++) t[q] = __bfloat162float(s_t[(lane+32*q)*68 + pos]);
        float s = t[0]+t[1]+t[2]+t[3];
        float sq = t[0]*t[0]+t[1]*t[1]+t[2]*t[2]+t[3]*t[3];
        #pragma unroll
        for (int o = 16; o; o >>= 1) {
            s  += __shfl_xor_sync(~0u, s,  o);
            sq += __shfl_xor_sync(~0u, sq, o);
        }
        float mu = s*(1.f/128.f), var = sq*(1.f/128.f) - mu*mu;
        float rstd = rsqrtf(var + 1e-5f);
        #pragma unroll
        for (int q = 0; q < 4; q++) {
            float v = (t[q]-mu)*rstd*lw[q] + lb[q];
            v *= g_ogate[(p0+pos)*128 + lane + 32*q];
            __nv_bfloat16 h = __float2bfloat16_rn(v);
            s_vh[pos*136 + lane + 32*q] = h;
            s_vl[pos*136 + lane + 32*q] = __float2bfloat16_rn(v - __bfloat162float(h));
        }
    }
    __syncthreads();  // LN reads of s_t done; safe to overwrite with w_out

    copy_w128(g_wh[5], g_wlo[5], s_wh, s_wl, tid);
    __syncthreads();

    float acc[2][4][4] = {};
    gemm_tile3<4>(acc, s_vh, s_vl, s_wh, s_wl, lane, wm*32, wn*32);

    #pragma unroll
    for (int mf = 0; mf < 2; mf++)
        #pragma unroll
        for (int nf = 0; nf < 4; nf++) {
            int row = wm*32 + mf*16 + (lane >> 2);
            int col = wn*32 + nf*8 + (lane & 3)*2;
            *(float2*)(out + (p0+row)*128 + col)   = make_float2(acc[mf][nf][0], acc[mf][nf][1]);
            *(float2*)(out + (p0+row+8)*128 + col) = make_float2(acc[mf][nf][2], acc[mf][nf][3]);
        }
}

// -----------------------------------------------------------------------------
extern "C" void kernel_launch(void* const* d_in, const int* in_sizes, int n_in,
                              void* d_out, int out_size) {
    (void)in_sizes; (void)n_in; (void)out_size;
    const float* x    = (const float*)d_in[0];
    const float* mask = (const float*)d_in[1];
    const float* nw   = (const float*)d_in[2];
    const float* nb   = (const float*)d_in[3];
    const float* wl   = (const float*)d_in[4];
    const float* wr   = (const float*)d_in[5];
    const float* wlg  = (const float*)d_in[6];
    const float* wrg  = (const float*)d_in[7];
    const float* wog  = (const float*)d_in[8];
    const float* onw  = (const float*)d_in[9];
    const float* onb  = (const float*)d_in[10];
    const float* wout = (const float*)d_in[11];
    float* out = (float*)d_out;

    cudaFuncSetAttribute(stage_a_fused, cudaFuncAttributeMaxDynamicSharedMemorySize, AM_SMEM);
    cudaFuncSetAttribute(stage_b,       cudaFuncAttributeMaxDynamicSharedMemorySize, SB_SMEM);
    cudaFuncSetAttribute(stage_cmm,     cudaFuncAttributeMaxDynamicSharedMemorySize, SC_SMEM);

    stage_wsplit<<<6, 256>>>(wl, wr, wlg, wrg, wog, wout);
    stage_a_fused<<<PP/64, 256, AM_SMEM>>>(x, mask, nw, nb);
    stage_b<<<dim3(36, 128), 256, SB_SMEM>>>();
    stage_cmm<<<PP/64, 256, SC_SMEM>>>(onw, onb, out);
}

// round 16
// speedup vs baseline: 1.0924x; 1.0315x over previous
#include <cuda_runtime.h>
#include <cuda_bf16.h>
#include <cstdint>

#define NN 768
#define PP (NN*NN)

__device__ __align__(256) __nv_bfloat16 g_left [(size_t)128 * PP]; // [h][i*N+k]
__device__ __align__(256) __nv_bfloat16 g_right[(size_t)128 * PP]; // [h][j*N+k]
__device__ __align__(256) __nv_bfloat16 g_pair [(size_t)128 * PP]; // [d][i*N+j]
__device__ __align__(256) float         g_ogate[(size_t)PP  * 128]; // [p][h]
__device__ __align__(256) __nv_bfloat16 g_wh[6][128*128];           // weight hi
__device__ __align__(256) __nv_bfloat16 g_wlo[6][128*128];          // weight lo

// ---------------- mma helpers ----------------
__device__ __forceinline__ void mma16816(float* c, const uint32_t* a, const uint32_t* b) {
    asm volatile("mma.sync.aligned.m16n8k16.row.col.f32.bf16.bf16.f32 "
                 "{%0,%1,%2,%3}, {%4,%5,%6,%7}, {%8,%9}, {%0,%1,%2,%3};\n"
                 : "+f"(c[0]), "+f"(c[1]), "+f"(c[2]), "+f"(c[3])
                 : "r"(a[0]), "r"(a[1]), "r"(a[2]), "r"(a[3]), "r"(b[0]), "r"(b[1]));
}
__device__ __forceinline__ void ldsm4(uint32_t* r, const void* p) {
    unsigned a = (unsigned)__cvta_generic_to_shared(p);
    asm volatile("ldmatrix.sync.aligned.m8n8.x4.shared.b16 {%0,%1,%2,%3}, [%4];\n"
                 : "=r"(r[0]), "=r"(r[1]), "=r"(r[2]), "=r"(r[3]) : "r"(a));
}
__device__ __forceinline__ void cpa16(void* dst, const void* src) {
    unsigned u = (unsigned)__cvta_generic_to_shared(dst);
    asm volatile("cp.async.cg.shared.global [%0], [%1], 16;\n" :: "r"(u), "l"(src) : "memory");
}
__device__ __forceinline__ void cp_commit() {
    asm volatile("cp.async.commit_group;\n" ::: "memory");
}
__device__ __forceinline__ void cp_wait0() {
    asm volatile("cp.async.wait_group 0;\n" ::: "memory");
}

// M(2x16) x N(NF x 8) x K128 split-bf16 GEMM: acc += X*W^T.
// Fused 3 passes (hh, hl, lh) per k-step: fragments loaded once, 3 mma each.
template<int NF>
__device__ __forceinline__ void gemm_tile3(
    float (&acc)[2][NF][4],
    const __nv_bfloat16* sXh, const __nv_bfloat16* sXl,
    const __nv_bfloat16* sWh, const __nv_bfloat16* sWl,
    int lane, int mbase, int nbase)
{
    const int lr  = lane & 15, lkA = (lane >> 4) << 3;
    const int bn  = lane & 7, bks = ((lane >> 3) & 1) << 3;
    const int bnf = lane >> 4;
    #pragma unroll
    for (int ks = 0; ks < 8; ks++) {
        uint32_t ah[2][4], al[2][4], bh[NF][2], bl[NF][2];
        #pragma unroll
        for (int mf = 0; mf < 2; mf++) {
            ldsm4(ah[mf], sXh + (mbase + mf*16 + lr)*136 + ks*16 + lkA);
            ldsm4(al[mf], sXl + (mbase + mf*16 + lr)*136 + ks*16 + lkA);
        }
        #pragma unroll
        for (int nf = 0; nf < NF; nf += 2) {
            uint32_t t[4];
            ldsm4(t, sWh + (nbase + (nf + bnf)*8 + bn)*136 + ks*16 + bks);
            bh[nf][0]=t[0]; bh[nf][1]=t[1]; bh[nf+1][0]=t[2]; bh[nf+1][1]=t[3];
            ldsm4(t, sWl + (nbase + (nf + bnf)*8 + bn)*136 + ks*16 + bks);
            bl[nf][0]=t[0]; bl[nf][1]=t[1]; bl[nf+1][0]=t[2]; bl[nf+1][1]=t[3];
        }
        #pragma unroll
        for (int mf = 0; mf < 2; mf++)
            #pragma unroll
            for (int nf = 0; nf < NF; nf++) {
                mma16816(acc[mf][nf], ah[mf], bh[nf]);
                mma16816(acc[mf][nf], ah[mf], bl[nf]);
                mma16816(acc[mf][nf], al[mf], bh[nf]);
            }
    }
}

// ---------------- Stage Wsplit: split 6 weight mats to bf16 hi/lo ----------------
__global__ void stage_wsplit(
    const float* __restrict__ wl, const float* __restrict__ wr,
    const float* __restrict__ wlg, const float* __restrict__ wrg,
    const float* __restrict__ wog, const float* __restrict__ wout)
{
    const float* Ws[6] = {wl, wr, wlg, wrg, wog, wout};
    const float* W = Ws[blockIdx.x];
    __nv_bfloat16* gh = g_wh[blockIdx.x];
    __nv_bfloat16* gl = g_wlo[blockIdx.x];
    for (int i = threadIdx.x; i < 128*128/2; i += 256) {
        float2 w = ((const float2*)W)[i];
        __nv_bfloat16 hx = __float2bfloat16_rn(w.x), hy = __float2bfloat16_rn(w.y);
        __nv_bfloat162 hp; hp.x = hx; hp.y = hy;
        ((__nv_bfloat162*)gh)[i] = hp;
        ((__nv_bfloat162*)gl)[i] =
            __floats2bfloat162_rn(w.x - __bfloat162float(hx), w.y - __bfloat162float(hy));
    }
}

// async copy of pre-split [128][128] weight hi/lo into smem (pitch 136), 256 thr
__device__ __forceinline__ void copy_w128_async(const __nv_bfloat16* __restrict__ gh,
                                                const __nv_bfloat16* __restrict__ gl,
                                                __nv_bfloat16* sh, __nv_bfloat16* sl, int tid) {
    #pragma unroll
    for (int q = 0; q < 8; q++) {
        int idx = tid + 256*q, row = idx >> 4, seg = (idx & 15) << 3;
        cpa16(sh + row*136 + seg, gh + row*128 + seg);
        cpa16(sl + row*136 + seg, gl + row*128 + seg);
    }
    cp_commit();
}
// sync copy (stage_cmm)
__device__ __forceinline__ void copy_w128(const __nv_bfloat16* __restrict__ gh,
                                          const __nv_bfloat16* __restrict__ gl,
                                          __nv_bfloat16* sh, __nv_bfloat16* sl, int tid) {
    #pragma unroll
    for (int q = 0; q < 8; q++) {
        int idx = tid + 256*q, row = idx >> 4, seg = (idx & 15) << 3;
        *(uint4*)(sh + row*136 + seg) = *(const uint4*)(gh + row*128 + seg);
        *(uint4*)(sl + row*136 + seg) = *(const uint4*)(gl + row*128 + seg);
    }
}

// ---- Stage A fused: LN + 5 projections + gating, X resident, M=64, 2 CTAs/SM ----
#define AM_SMEM (2*17408 + 2*34816)   // 102 KB

__global__ __launch_bounds__(256, 2) void stage_a_fused(
    const float* __restrict__ x,   const float* __restrict__ mask,
    const float* __restrict__ nw,  const float* __restrict__ nb)
{
    extern __shared__ __nv_bfloat16 smem[];
    __nv_bfloat16* sXh = smem;            // [64][136]  (live whole kernel)
    __nv_bfloat16* sXl = smem + 8704;
    __nv_bfloat16* sWh = smem + 17408;    // [128][136] (recycled per weight)
    __nv_bfloat16* sWl = smem + 34816;

    const int tid = threadIdx.x, lane = tid & 31, warp = tid >> 5;
    const int wm = warp & 1, wn = warp >> 1;
    const size_t pbase = (size_t)blockIdx.x * 64;

    // Prefetch mat0 weights (wl) — overlaps the whole LN phase
    copy_w128_async(g_wh[0], g_wlo[0], sWh, sWl, tid);

    { // LayerNorm straight from gmem into sXh/sXl, warp per position
        float4 w4 = ((const float4*)nw)[lane], b4 = ((const float4*)nb)[lane];
        #pragma unroll 1
        for (int pp = 0; pp < 8; pp++) {
            int pos = warp*8 + pp;
            float4 v = ((const float4*)(x + (pbase+pos)*128))[lane];
            float s  = v.x+v.y+v.z+v.w;
            float sq = v.x*v.x+v.y*v.y+v.z*v.z+v.w*v.w;
            #pragma unroll
            for (int o = 16; o; o >>= 1) {
                s  += __shfl_xor_sync(~0u, s,  o);
                sq += __shfl_xor_sync(~0u, sq, o);
            }
            float mu = s*(1.f/128.f), var = sq*(1.f/128.f) - mu*mu;
            float rstd = rsqrtf(var + 1e-5f);
            v.x=(v.x-mu)*rstd*w4.x+b4.x; v.y=(v.y-mu)*rstd*w4.y+b4.y;
            v.z=(v.z-mu)*rstd*w4.z+b4.z; v.w=(v.w-mu)*rstd*w4.w+b4.w;
            __nv_bfloat16 hx=__float2bfloat16_rn(v.x), hy=__float2bfloat16_rn(v.y);
            __nv_bfloat16 hz=__float2bfloat16_rn(v.z), hw=__float2bfloat16_rn(v.w);
            __nv_bfloat162 h01; h01.x=hx; h01.y=hy;
            __nv_bfloat162 h23; h23.x=hz; h23.y=hw;
            __nv_bfloat162 l01 = __floats2bfloat162_rn(v.x-__bfloat162float(hx), v.y-__bfloat162float(hy));
            __nv_bfloat162 l23 = __floats2bfloat162_rn(v.z-__bfloat162float(hz), v.w-__bfloat162float(hw));
            *(__nv_bfloat162*)(sXh + pos*136 + lane*4)     = h01;
            *(__nv_bfloat162*)(sXh + pos*136 + lane*4 + 2) = h23;
            *(__nv_bfloat162*)(sXl + pos*136 + lane*4)     = l01;
            *(__nv_bfloat162*)(sXl + pos*136 + lane*4 + 2) = l23;
        }
    }

    float mrow[2][2];
    #pragma unroll
    for (int mf = 0; mf < 2; mf++) {
        int r = wm*32 + mf*16 + (lane >> 2);
        mrow[mf][0] = mask[pbase + r];
        mrow[mf][1] = mask[pbase + r + 8];
    }

    #pragma unroll 1
    for (int mat = 0; mat < 3; mat++) {
        const bool dual = (mat < 2);
        const int ib = (mat==0) ? 2 : 3;                  // wlg, wrg

        cp_wait0();
        __syncthreads();                 // X + WA ready; prior epilogue done
        float accA[2][4][4] = {};
        gemm_tile3<4>(accA, sXh, sXl, sWh, sWl, lane, wm*32, wn*32);

        if (dual) {
            __syncthreads();             // all WA reads done
            copy_w128_async(g_wh[ib], g_wlo[ib], sWh, sWl, tid);
            cp_wait0();
            __syncthreads();
            float accB[2][4][4] = {};
            gemm_tile3<4>(accB, sXh, sXl, sWh, sWl, lane, wm*32, wn*32);

            __nv_bfloat16* s_stage = sWh;  // [128 h][68 pos], W dead after gemms
            __syncthreads();
            #pragma unroll
            for (int mf = 0; mf < 2; mf++)
                #pragma unroll
                for (int nf = 0; nf < 4; nf++) {
                    int row = wm*32 + mf*16 + (lane >> 2);
                    int col = wn*32 + nf*8 + (lane & 3)*2;
                    float g0 = 1.f/(1.f+__expf(-accB[mf][nf][0]));
                    float g1 = 1.f/(1.f+__expf(-accB[mf][nf][1]));
                    float g2 = 1.f/(1.f+__expf(-accB[mf][nf][2]));
                    float g3 = 1.f/(1.f+__expf(-accB[mf][nf][3]));
                    s_stage[ col   *68 + row  ] = __float2bfloat16(accA[mf][nf][0]*mrow[mf][0]*g0);
                    s_stage[(col+1)*68 + row  ] = __float2bfloat16(accA[mf][nf][1]*mrow[mf][0]*g1);
                    s_stage[ col   *68 + row+8] = __float2bfloat16(accA[mf][nf][2]*mrow[mf][1]*g2);
                    s_stage[(col+1)*68 + row+8] = __float2bfloat16(accA[mf][nf][3]*mrow[mf][1]*g3);
                }
            __syncthreads();
            __nv_bfloat16* gdst = (mat == 0) ? g_left : g_right;
            #pragma unroll
            for (int q = 0; q < 8; q++) {
                int idx = tid + 256*q, hh = idx >> 4, seg = (idx & 15) << 2;
                *(uint2*)(gdst + (size_t)hh*PP + pbase + seg) =
                    *(const uint2*)(s_stage + hh*68 + seg);
            }
            __syncthreads();             // s_stage reads done before next W copy
            const int nxt = (mat==0) ? 1 : 4;   // wr, wog
            copy_w128_async(g_wh[nxt], g_wlo[nxt], sWh, sWl, tid);
        } else {
            #pragma unroll
            for (int mf = 0; mf < 2; mf++)
                #pragma unroll
                for (int nf = 0; nf < 4; nf++) {
                    int row = wm*32 + mf*16 + (lane >> 2);
                    int col = wn*32 + nf*8 + (lane & 3)*2;
                    float2 p0 = make_float2(1.f/(1.f+__expf(-accA[mf][nf][0])),
                                            1.f/(1.f+__expf(-accA[mf][nf][1])));
                    float2 p1 = make_float2(1.f/(1.f+__expf(-accA[mf][nf][2])),
                                            1.f/(1.f+__expf(-accA[mf][nf][3])));
                    *(float2*)(g_ogate + (pbase+row)*128 + col)   = p0;
                    *(float2*)(g_ogate + (pbase+row+8)*128 + col) = p1;
                }
        }
    }
}

// -------- Stage B: per-channel bf16 einsum, k-chunk 64, one sync/iter --------
#define SB_SMEM (4*128*72*2)   // 73728 B -> 2 CTAs/SM

__device__ __forceinline__ void sb_issue(const __nv_bfloat16* gA, const __nv_bfloat16* gB,
                                         __nv_bfloat16* sA, __nv_bfloat16* sB, int tid, int k0) {
    #pragma unroll
    for (int q = 0; q < 4; q++) {
        int idx = tid + 256*q, row = idx >> 3, seg = (idx & 7) << 3;
        cpa16(sA + row*72 + seg, gA + (size_t)row*NN + k0 + seg);
        cpa16(sB + row*72 + seg, gB + (size_t)row*NN + k0 + seg);
    }
    cp_commit();
}

__global__ __launch_bounds__(256, 2) void stage_b() {
    extern __shared__ __nv_bfloat16 smb[];
    __nv_bfloat16* sA = smb;              // [2 buf][128][72]
    __nv_bfloat16* sB = smb + 2*128*72;

    const int tid = threadIdx.x, lane = tid & 31, warp = tid >> 5;
    const int wm = warp & 1, wn = warp >> 1;
    const int d = blockIdx.y, ti = blockIdx.x / 6, tj = blockIdx.x % 6;
    const __nv_bfloat16* gA = g_left  + (size_t)d*PP + (size_t)(ti*128)*NN;
    const __nv_bfloat16* gB = g_right + (size_t)d*PP + (size_t)(tj*128)*NN;

    const int lr  = lane & 15, lkA = (lane >> 4) << 3;
    const int bn  = lane & 7, bks = ((lane >> 3) & 1) << 3;
    const int bnf = lane >> 4;

    float c[4][4][4] = {};
    sb_issue(gA, gB, sA, sB, tid, 0);

    #pragma unroll 1
    for (int kt = 0; kt < 12; kt++) {
        int buf = kt & 1;
        cp_wait0();
        __syncthreads();   // chunk kt visible; all warps done reading buf^1
        if (kt < 11)
            sb_issue(gA, gB, sA + (buf^1)*9216, sB + (buf^1)*9216, tid, (kt+1)*64);
        const __nv_bfloat16* Ab = sA + buf*9216;
        const __nv_bfloat16* Bb = sB + buf*9216;
        #pragma unroll
        for (int kk = 0; kk < 4; kk++) {
            uint32_t a[4][4], b[4][2];
            #pragma unroll
            for (int fm = 0; fm < 4; fm++)
                ldsm4(a[fm], Ab + (wm*64 + fm*16 + lr)*72 + kk*16 + lkA);
            #pragma unroll
            for (int nf = 0; nf < 4; nf += 2) {
                uint32_t t[4];
                ldsm4(t, Bb + (wn*32 + (nf + bnf)*8 + bn)*72 + kk*16 + bks);
                b[nf][0]=t[0]; b[nf][1]=t[1]; b[nf+1][0]=t[2]; b[nf+1][1]=t[3];
            }
            #pragma unroll
            for (int fm = 0; fm < 4; fm++)
                #pragma unroll
                for (int fn = 0; fn < 4; fn++) mma16816(c[fm][fn], a[fm], b[fn]);
        }
    }

    __nv_bfloat16* gO = g_pair + (size_t)d*PP;
    #pragma unroll
    for (int fm = 0; fm < 4; fm++)
        #pragma unroll
        for (int fn = 0; fn < 4; fn++) {
            int r0 = ti*128 + wm*64 + fm*16 + (lane >> 2);
            int cc = tj*128 + wn*32 + fn*8 + (lane & 3)*2;
            *(__nv_bfloat162*)(gO + (size_t)r0*NN + cc) =
                __float22bfloat162_rn(make_float2(c[fm][fn][0], c[fm][fn][1]));
            *(__nv_bfloat162*)(gO + (size_t)(r0+8)*NN + cc) =
                __float22bfloat162_rn(make_float2(c[fm][fn][2], c[fm][fn][3]));
        }
}

// ------ Stage C (mma): LN over H + out_gate + final projection, M=64 ------
// Pair tile pitch 66 (33 words, gcd(33,32)=1 -> conflict-free LN reads);
// gate tile prefetched via cp.async into the dead s_wl region.
#define SC_SMEM (2*17408 + 2*34816)   // 102 KB -> 2 CTAs/SM

__global__ __launch_bounds__(256, 2) void stage_cmm(
    const float* __restrict__ onw, const float* __restrict__ onb,
    float* __restrict__ out)
{
    extern __shared__ __nv_bfloat16 smc[];
    __nv_bfloat16* s_vh = smc;            // [64 pos][136]
    __nv_bfloat16* s_vl = smc + 8704;
    __nv_bfloat16* s_wh = smc + 17408;    // [128 dout][136]
    __nv_bfloat16* s_wl = smc + 34816;
    __nv_bfloat16* s_t  = s_wh;           // [128 d][66] overlay (16892 B < 17408)
    float*         s_og = (float*)s_wl;   // [64 pos][128] fp32 overlay (32768 B < 34816)

    const int tid = threadIdx.x, lane = tid & 31, warp = tid >> 5;
    const int wm = warp & 1, wn = warp >> 1;
    const size_t p0 = (size_t)blockIdx.x * 64;

    // gate tile prefetch: [64 pos][128 h] fp32, 16B chunks
    #pragma unroll
    for (int q = 0; q < 8; q++) {
        int idx = tid + 256*q, r = idx >> 5, c4 = (idx & 31) << 2;
        cpa16(s_og + r*128 + c4, g_ogate + (p0 + r)*128 + c4);
    }
    cp_commit();

    #pragma unroll
    for (int q = 0; q < 16; q++) { // pair tile [128 d][64 pos], pitch 66, uint loads
        int idx = tid + 256*q, dd = idx >> 5, seg = idx & 31;
        ((uint32_t*)s_t)[dd*33 + seg] =
            ((const uint32_t*)(g_pair + (size_t)dd*PP + p0))[seg];
    }
    cp_wait0();
    __syncthreads();

    float lw[4], lb[4];
    #pragma unroll
    for (int q = 0; q < 4; q++) { lw[q] = onw[lane+32*q]; lb[q] = onb[lane+32*q]; }

    #pragma unroll 1
    for (int pp = 0; pp < 8; pp++) { // LN over d + gate, warp per position
        int pos = warp*8 + pp;
        float t[4];
        #pragma unroll
        for (int q = 0; q < 4; q++) t[q] = __bfloat162float(s_t[(lane+32*q)*66 + pos]);
        float s = t[0]+t[1]+t[2]+t[3];
        float sq = t[0]*t[0]+t[1]*t[1]+t[2]*t[2]+t[3]*t[3];
        #pragma unroll
        for (int o = 16; o; o >>= 1) {
            s  += __shfl_xor_sync(~0u, s,  o);
            sq += __shfl_xor_sync(~0u, sq, o);
        }
        float mu = s*(1.f/128.f), var = sq*(1.f/128.f) - mu*mu;
        float rstd = rsqrtf(var + 1e-5f);
        #pragma unroll
        for (int q = 0; q < 4; q++) {
            float v = (t[q]-mu)*rstd*lw[q] + lb[q];
            v *= s_og[pos*128 + lane + 32*q];
            __nv_bfloat16 h = __float2bfloat16_rn(v);
            s_vh[pos*136 + lane + 32*q] = h;
            s_vl[pos*136 + lane + 32*q] = __float2bfloat16_rn(v - __bfloat162float(h));
        }
    }
    __syncthreads();  // LN reads of s_t/s_og done; safe to overwrite with w_out

    copy_w128(g_wh[5], g_wlo[5], s_wh, s_wl, tid);
    __syncthreads();

    float acc[2][4][4] = {};
    gemm_tile3<4>(acc, s_vh, s_vl, s_wh, s_wl, lane, wm*32, wn*32);

    #pragma unroll
    for (int mf = 0; mf < 2; mf++)
        #pragma unroll
        for (int nf = 0; nf < 4; nf++) {
            int row = wm*32 + mf*16 + (lane >> 2);
            int col = wn*32 + nf*8 + (lane & 3)*2;
            *(float2*)(out + (p0+row)*128 + col)   = make_float2(acc[mf][nf][0], acc[mf][nf][1]);
            *(float2*)(out + (p0+row+8)*128 + col) = make_float2(acc[mf][nf][2], acc[mf][nf][3]);
        }
}

// -----------------------------------------------------------------------------
extern "C" void kernel_launch(void* const* d_in, const int* in_sizes, int n_in,
                              void* d_out, int out_size) {
    (void)in_sizes; (void)n_in; (void)out_size;
    const float* x    = (const float*)d_in[0];
    const float* mask = (const float*)d_in[1];
    const float* nw   = (const float*)d_in[2];
    const float* nb   = (const float*)d_in[3];
    const float* wl   = (const float*)d_in[4];
    const float* wr   = (const float*)d_in[5];
    const float* wlg  = (const float*)d_in[6];
    const float* wrg  = (const float*)d_in[7];
    const float* wog  = (const float*)d_in[8];
    const float* onw  = (const float*)d_in[9];
    const float* onb  = (const float*)d_in[10];
    const float* wout = (const float*)d_in[11];
    float* out = (float*)d_out;

    cudaFuncSetAttribute(stage_a_fused, cudaFuncAttributeMaxDynamicSharedMemorySize, AM_SMEM);
    cudaFuncSetAttribute(stage_b,       cudaFuncAttributeMaxDynamicSharedMemorySize, SB_SMEM);
    cudaFuncSetAttribute(stage_cmm,     cudaFuncAttributeMaxDynamicSharedMemorySize, SC_SMEM);

    stage_wsplit<<<6, 256>>>(wl, wr, wlg, wrg, wog, wout);
    stage_a_fused<<<PP/64, 256, AM_SMEM>>>(x, mask, nw, nb);
    stage_b<<<dim3(36, 128), 256, SB_SMEM>>>();
    stage_cmm<<<PP/64, 256, SC_SMEM>>>(onw, onb, out);
}